// round 15
// baseline (speedup 1.0000x reference)
#include <cuda_runtime.h>
#include <cuda_fp16.h>
#include <cstdint>
#include <math.h>

#define NB 32768      // tokens
#define ND 768        // model dim
#define NH 3072       // hidden dim
#define NE 8          // experts
#define BM 128
#define BN 128
#define BK 32
#define MAX_TILES ((NB * 2) / BM + NE)   // 520
#define PAD_ROWS (MAX_TILES * BM)        // 66560

#define OP_LD 40      // smem row stride (elements): 32 data + 8 pad = 80B

// ---------------- scratch (device globals; referenced ONLY by name in device
// code — never passed as kernel arguments from host) --------------------------
__device__ __half g_a16[(size_t)PAD_ROWS * ND];    // fp16(x) gathered pair rows
__device__ __half g_h16[(size_t)PAD_ROWS * NH];    // fp16(relu(h)) activations
__device__ float  g_outp[(size_t)PAD_ROWS * ND];   // per-pair expert outputs
__device__ __half g_w1t[(size_t)NE * NH * ND];     // [e][n][k] fp16
__device__ __half g_w2t[(size_t)NE * ND * NH];     // [e][n][k] fp16
__device__ int   g_pair_token[PAD_ROWS];
__device__ int   g_pairpos[NB * 2];
__device__ float g_wts[NB * 2];
__device__ int   g_eidx[NB * 2];
__device__ int   g_counts[NE];
__device__ int   g_cursor[NE];
__device__ int   g_offsets[NE];
__device__ int   g_tile_expert[MAX_TILES];
__device__ int   g_tile_segend[MAX_TILES];

// ---------------- PTX helpers ------------------------------------------------
__device__ __forceinline__ uint32_t smem_to_u32(const void* p) {
    uint32_t a;
    asm("{ .reg .u64 t; cvta.to.shared.u64 t, %1; cvt.u32.u64 %0, t; }"
        : "=r"(a) : "l"(p));
    return a;
}
__device__ __forceinline__ void cp_async16(uint32_t smem, const void* g) {
    asm volatile("cp.async.cg.shared.global [%0], [%1], 16;" :: "r"(smem), "l"(g));
}
#define CP_COMMIT() asm volatile("cp.async.commit_group;" ::: "memory")
#define CP_WAIT(n)  asm volatile("cp.async.wait_group %0;" :: "n"(n) : "memory")

// fp32-accumulate HMMA (proven path, GEMM2)
#define MMA_F16(d, a, b) \
    asm volatile("mma.sync.aligned.m16n8k16.row.col.f32.f16.f16.f32 " \
        "{%0,%1,%2,%3}, {%4,%5,%6,%7}, {%8,%9}, {%0,%1,%2,%3};" \
        : "+f"((d)[0]), "+f"((d)[1]), "+f"((d)[2]), "+f"((d)[3]) \
        : "r"((a)[0]), "r"((a)[1]), "r"((a)[2]), "r"((a)[3]), \
          "r"((b)[0]), "r"((b)[1]))

// fp16-accumulate HMMA probe (GEMM1): d = a*b + c, all f16
#define MMA_F16ACC(d, a, b, c0, c1) \
    asm volatile("mma.sync.aligned.m16n8k16.row.col.f16.f16.f16.f16 " \
        "{%0,%1}, {%2,%3,%4,%5}, {%6,%7}, {%8,%9};" \
        : "=r"((d)[0]), "=r"((d)[1]) \
        : "r"((a)[0]), "r"((a)[1]), "r"((a)[2]), "r"((a)[3]), \
          "r"((b)[0]), "r"((b)[1]), "r"(c0), "r"(c1))

// ---------------- init / gating / routing (proven) ---------------------------
__global__ void init_kernel() {
    if (threadIdx.x < NE) g_counts[threadIdx.x] = 0;
}

__global__ void gating_kernel(const float* __restrict__ x,
                              const float* __restrict__ Wg,
                              const float* __restrict__ bg) {
    int warp = (blockIdx.x * blockDim.x + threadIdx.x) >> 5;
    int lane = threadIdx.x & 31;
    if (warp >= NB) return;
    const float* xr = x + (size_t)warp * ND;
    float acc[8];
#pragma unroll
    for (int i = 0; i < 8; ++i) acc[i] = 0.f;
#pragma unroll 4
    for (int j = 0; j < ND / 32; ++j) {
        int d = j * 32 + lane;
        float xv = xr[d];
        const float* wr = Wg + (size_t)d * NE;
        float4 w0 = *(const float4*)(wr);
        float4 w1 = *(const float4*)(wr + 4);
        acc[0] += xv * w0.x; acc[1] += xv * w0.y;
        acc[2] += xv * w0.z; acc[3] += xv * w0.w;
        acc[4] += xv * w1.x; acc[5] += xv * w1.y;
        acc[6] += xv * w1.z; acc[7] += xv * w1.w;
    }
#pragma unroll
    for (int i = 0; i < 8; ++i)
#pragma unroll
        for (int off = 16; off > 0; off >>= 1)
            acc[i] += __shfl_xor_sync(0xFFFFFFFFu, acc[i], off);
    if (lane == 0) {
        float l[8];
#pragma unroll
        for (int i = 0; i < 8; ++i) l[i] = acc[i] + bg[i];
        int e0 = 0; float v0 = l[0];
#pragma unroll
        for (int i = 1; i < 8; ++i)
            if (l[i] > v0) { v0 = l[i]; e0 = i; }
        int e1 = -1; float v1 = -1e30f;
#pragma unroll
        for (int i = 0; i < 8; ++i)
            if (i != e0 && l[i] > v1) { v1 = l[i]; e1 = i; }
        float t  = expf(v1 - v0);
        float w0 = 1.f / (1.f + t);
        float w1 = t / (1.f + t);
        g_eidx[warp * 2 + 0] = e0;
        g_eidx[warp * 2 + 1] = e1;
        g_wts[warp * 2 + 0]  = w0;
        g_wts[warp * 2 + 1]  = w1;
        atomicAdd(&g_counts[e0], 1);
        atomicAdd(&g_counts[e1], 1);
    }
}

__global__ void route_build_kernel() {
    if (threadIdx.x == 0 && blockIdx.x == 0) {
        int off = 0, tile = 0;
        for (int e = 0; e < NE; ++e) {
            g_offsets[e] = off;
            g_cursor[e]  = 0;
            int c  = g_counts[e];
            int nt = (c + BM - 1) / BM;
            for (int i = 0; i < nt; ++i) {
                g_tile_expert[tile] = e;
                g_tile_segend[tile] = off + c;
                ++tile;
            }
            off += nt * BM;
        }
        for (; tile < MAX_TILES; ++tile) { g_tile_expert[tile] = -1; g_tile_segend[tile] = 0; }
    }
}

__global__ void assign_kernel() {
    int tid = blockIdx.x * blockDim.x + threadIdx.x;
    if (tid >= NB * 2) return;
    int b = tid >> 1;
    int e = g_eidx[tid];
    int pos = g_offsets[e] + atomicAdd(&g_cursor[e], 1);
    g_pair_token[pos] = b;
    g_pairpos[tid]    = pos;
}

// ---------------- gather x -> fp16 pair rows ---------------------------------
__global__ void gather_kernel(const float* __restrict__ x) {
    const int PER_ROW = ND / 8;
    int idx = blockIdx.x * blockDim.x + threadIdx.x;
    if (idx >= PAD_ROWS * PER_ROW) return;
    int r = idx / PER_ROW;
    int j = idx - r * PER_ROW;
    int rt = r >> 7;
    int tokv = -1;
    if (g_tile_expert[rt] >= 0 && r < g_tile_segend[rt]) tokv = g_pair_token[r];

    ushort h16[8];
    if (tokv >= 0) {
        const float* xp = x + (size_t)tokv * ND + j * 8;
        float4 a = *(const float4*)xp;
        float4 b = *(const float4*)(xp + 4);
        float v[8] = {a.x, a.y, a.z, a.w, b.x, b.y, b.z, b.w};
#pragma unroll
        for (int i = 0; i < 8; ++i)
            h16[i] = __half_as_ushort(__float2half_rn(v[i]));
    } else {
#pragma unroll
        for (int i = 0; i < 8; ++i) h16[i] = 0;
    }
    *(uint4*)(g_a16 + (size_t)r * ND + j * 8) = *(uint4*)h16;
}

// ---------------- weight transpose+convert: W[e][K][N] -> [e][N][K] fp16 -----
template<bool IS_W1>
__global__ void wconv_kernel(const float* __restrict__ W, int K, int N) {
    __shared__ float tile[32][33];
    __half* o = IS_W1 ? g_w1t : g_w2t;
    int e = blockIdx.z;
    const float* Win = W + (size_t)e * K * N;
    __half* oe = o + (size_t)e * K * N;
    int n0 = blockIdx.x * 32, k0 = blockIdx.y * 32;
    int tx = threadIdx.x, ty = threadIdx.y;
#pragma unroll
    for (int j = 0; j < 4; ++j)
        tile[ty + j * 8][tx] = Win[(size_t)(k0 + ty + j * 8) * N + n0 + tx];
    __syncthreads();
#pragma unroll
    for (int j = 0; j < 4; ++j) {
        float v = tile[tx][ty + j * 8];
        oe[(size_t)(n0 + ty + j * 8) * K + k0 + tx] = __float2half_rn(v);
    }
}

// ---------------- single-product fp16 HMMA GEMM ------------------------------
// 256 threads = 8 warps 2(m) x 4(n); warp tile 64x32; BK=32 (2 k-steps).
// ACC16 (GEMM1 probe): fp16-accumulate HMMA chained across the chunk's 2
// k-steps, promoted to fp32 once per chunk per accumulator.
// !ACC16 (GEMM2): proven fp32-accumulate path.
template<int KTOT, bool IS_GEMM1, bool ACC16>
__global__ __launch_bounds__(256, 2) void gemm_mma_kernel(
    const float* __restrict__ bias_all,  // b1 or b2 (harness pointer)
    int NTOT) {

    __shared__ __half sA[2][BM * OP_LD];
    __shared__ __half sB[2][BN * OP_LD];

    const __half* Ain = IS_GEMM1 ? g_a16 : g_h16;
    const __half* Bin = IS_GEMM1 ? g_w1t : g_w2t;

    int rt = blockIdx.y;
    int e  = g_tile_expert[rt];
    if (e < 0) return;
    int seg_end = g_tile_segend[rt];
    int r0 = rt * BM;
    int n0 = blockIdx.x * BN;

    int t = threadIdx.x;
    int lane = t & 31;
    int warp = t >> 5;
    int m_base = (warp & 1) * 64;
    int n_base = (warp >> 1) * 32;
    int g4   = lane >> 2;   // 0..7
    int tid4 = lane & 3;    // 0..3

    const float* bias_e = bias_all + (size_t)e * NTOT + n0;
    uint32_t uA = smem_to_u32(sA);
    uint32_t uB = smem_to_u32(sB);
    const uint32_t stage_b = BM * OP_LD * 2;   // bytes per stage

    auto issue = [&](int c, int s) {
        uint32_t off = (uint32_t)s * stage_b;
        int koff = c * BK;
#pragma unroll
        for (int r = 0; r < 2; ++r) {
            int idx = t + r * 256;
            int row = idx >> 2;
            int ch  = idx & 3;
            uint32_t so = (uint32_t)(row * (OP_LD * 2) + ch * 16);
            cp_async16(uA + off + so,
                       Ain + (size_t)(r0 + row) * KTOT + koff + ch * 8);
            cp_async16(uB + off + so,
                       Bin + ((size_t)e * NTOT + n0 + row) * KTOT + koff + ch * 8);
        }
    };

    float acc[4][4][4];
#pragma unroll
    for (int i = 0; i < 4; ++i)
#pragma unroll
        for (int j = 0; j < 4; ++j)
#pragma unroll
            for (int q = 0; q < 4; ++q) acc[i][j][q] = 0.f;

    const int NC = KTOT / BK;

    issue(0, 0); CP_COMMIT();

    for (int c = 0; c < NC; ++c) {
        int s = c & 1;
        if (c + 1 < NC) {
            issue(c + 1, s ^ 1); CP_COMMIT();
            CP_WAIT(1);
        } else {
            CP_WAIT(0);
        }
        __syncthreads();

        const __half* pA = sA[s];
        const __half* pB = sB[s];

        if (ACC16) {
            // preload B frags for both k-steps, all j
            uint32_t fb[2][4][2];
#pragma unroll
            for (int ks = 0; ks < 2; ++ks)
#pragma unroll
                for (int j = 0; j < 4; ++j) {
                    int nrow = (n_base + j * 8 + g4) * OP_LD + ks * 16 + tid4 * 2;
                    fb[ks][j][0] = *(const uint32_t*)&pB[nrow];
                    fb[ks][j][1] = *(const uint32_t*)&pB[nrow + 8];
                }
#pragma unroll
            for (int i = 0; i < 4; ++i) {
                uint32_t fa0[4], fa1[4];
                int rb = (m_base + i * 16 + g4) * OP_LD + tid4 * 2;
                fa0[0] = *(const uint32_t*)&pA[rb];
                fa0[1] = *(const uint32_t*)&pA[rb + 8 * OP_LD];
                fa0[2] = *(const uint32_t*)&pA[rb + 8];
                fa0[3] = *(const uint32_t*)&pA[rb + 8 * OP_LD + 8];
                fa1[0] = *(const uint32_t*)&pA[rb + 16];
                fa1[1] = *(const uint32_t*)&pA[rb + 8 * OP_LD + 16];
                fa1[2] = *(const uint32_t*)&pA[rb + 24];
                fa1[3] = *(const uint32_t*)&pA[rb + 8 * OP_LD + 24];
#pragma unroll
                for (int j = 0; j < 4; ++j) {
                    uint32_t d16[2];
                    MMA_F16ACC(d16, fa0, fb[0][j], 0u, 0u);          // c = 0
                    MMA_F16ACC(d16, fa1, fb[1][j], d16[0], d16[1]);  // chain
                    float2 f0 = __half22float2(*(__half2*)&d16[0]);
                    float2 f1 = __half22float2(*(__half2*)&d16[1]);
                    acc[i][j][0] += f0.x;
                    acc[i][j][1] += f0.y;
                    acc[i][j][2] += f1.x;
                    acc[i][j][3] += f1.y;
                }
            }
        } else {
#pragma unroll
            for (int ks = 0; ks < 2; ++ks) {
                int kadd = ks * 16;
                uint32_t fb[4][2];
#pragma unroll
                for (int j = 0; j < 4; ++j) {
                    int nrow = (n_base + j * 8 + g4) * OP_LD + kadd + tid4 * 2;
                    fb[j][0] = *(const uint32_t*)&pB[nrow];
                    fb[j][1] = *(const uint32_t*)&pB[nrow + 8];
                }
#pragma unroll
                for (int i = 0; i < 4; ++i) {
                    uint32_t fa[4];
                    int rlo = (m_base + i * 16 + g4) * OP_LD + kadd + tid4 * 2;
                    int rhi = rlo + 8 * OP_LD;
                    fa[0] = *(const uint32_t*)&pA[rlo];
                    fa[1] = *(const uint32_t*)&pA[rhi];
                    fa[2] = *(const uint32_t*)&pA[rlo + 8];
                    fa[3] = *(const uint32_t*)&pA[rhi + 8];
#pragma unroll
                    for (int j = 0; j < 4; ++j) MMA_F16(acc[i][j], fa, fb[j]);
                }
            }
        }
        __syncthreads();
    }

    // ---- epilogue: direct from accumulator regs -----------------------------
#pragma unroll
    for (int j = 0; j < 4; ++j) {
        int coll = n_base + j * 8 + tid4 * 2;
        float b0 = bias_e[coll];
        float b1 = bias_e[coll + 1];
        int gcol = n0 + coll;
#pragma unroll
        for (int i = 0; i < 4; ++i) {
            int row0 = r0 + m_base + i * 16 + g4;
            int row1 = row0 + 8;
            float v0 = acc[i][j][0] + b0;
            float v1 = acc[i][j][1] + b1;
            float v2 = acc[i][j][2] + b0;
            float v3 = acc[i][j][3] + b1;
            if (IS_GEMM1) {
                v0 = fmaxf(v0, 0.f); v1 = fmaxf(v1, 0.f);
                v2 = fmaxf(v2, 0.f); v3 = fmaxf(v3, 0.f);
                if (row0 < seg_end) {
                    uint32_t p = (uint32_t)__half_as_ushort(__float2half_rn(v0)) |
                                 ((uint32_t)__half_as_ushort(__float2half_rn(v1)) << 16);
                    *(uint32_t*)(g_h16 + (size_t)row0 * NH + gcol) = p;
                }
                if (row1 < seg_end) {
                    uint32_t p = (uint32_t)__half_as_ushort(__float2half_rn(v2)) |
                                 ((uint32_t)__half_as_ushort(__float2half_rn(v3)) << 16);
                    *(uint32_t*)(g_h16 + (size_t)row1 * NH + gcol) = p;
                }
            } else {
                if (row0 < seg_end) {
                    float2 p; p.x = v0; p.y = v1;
                    *(float2*)(g_outp + (size_t)row0 * ND + gcol) = p;
                }
                if (row1 < seg_end) {
                    float2 p; p.x = v2; p.y = v3;
                    *(float2*)(g_outp + (size_t)row1 * ND + gcol) = p;
                }
            }
        }
    }
}

// ---------------- combine ----------------------------------------------------
__global__ void combine_kernel(float* __restrict__ y) {
    const int QD = ND / 4;
    int tid = blockIdx.x * blockDim.x + threadIdx.x;
    if (tid >= NB * QD) return;
    int b = tid / QD;
    int q = tid - b * QD;
    int p0 = g_pairpos[b * 2 + 0];
    int p1 = g_pairpos[b * 2 + 1];
    float w0 = g_wts[b * 2 + 0];
    float w1 = g_wts[b * 2 + 1];
    float4 o0 = ((const float4*)(g_outp + (size_t)p0 * ND))[q];
    float4 o1 = ((const float4*)(g_outp + (size_t)p1 * ND))[q];
    float4 r;
    r.x = w0 * o0.x + w1 * o1.x;
    r.y = w0 * o0.y + w1 * o1.y;
    r.z = w0 * o0.z + w1 * o1.z;
    r.w = w0 * o0.w + w1 * o1.w;
    ((float4*)y)[tid] = r;
}

// ---------------- launch ------------------------------------------------------
extern "C" void kernel_launch(void* const* d_in, const int* in_sizes, int n_in,
                              void* d_out, int out_size) {
    const float* x  = (const float*)d_in[0];
    const float* Wg = (const float*)d_in[1];
    const float* bg = (const float*)d_in[2];
    const float* W1 = (const float*)d_in[3];
    const float* b1 = (const float*)d_in[4];
    const float* W2 = (const float*)d_in[5];
    const float* b2 = (const float*)d_in[6];
    float* y = (float*)d_out;

    init_kernel<<<1, 32>>>();
    gating_kernel<<<(NB * 32) / 256, 256>>>(x, Wg, bg);
    route_build_kernel<<<1, 1>>>();
    assign_kernel<<<(NB * 2) / 256, 256>>>();

    // one-time conversions
    {
        dim3 g(NH / 32, ND / 32, NE);
        wconv_kernel<true><<<g, dim3(32, 8)>>>(W1, ND, NH);
    }
    {
        dim3 g(ND / 32, NH / 32, NE);
        wconv_kernel<false><<<g, dim3(32, 8)>>>(W2, NH, ND);
    }
    {
        int total = PAD_ROWS * (ND / 8);
        gather_kernel<<<(total + 255) / 256, 256>>>(x);
    }

    // GEMM1 (fp16-acc probe): relu(fp16(x) @ fp16(W1) + b1) -> g_h16
    {
        dim3 g(NH / BN, MAX_TILES);
        gemm_mma_kernel<ND, true, true><<<g, 256>>>(b1, NH);
    }
    // GEMM2 (fp32-acc, proven): g_h16 @ fp16(W2) + b2 -> g_outp
    {
        dim3 g(ND / BN, MAX_TILES);
        gemm_mma_kernel<NH, false, false><<<g, 256>>>(b2, ND);
    }

    combine_kernel<<<(NB * (ND / 4) + 255) / 256, 256>>>(y);
}

// round 16
// speedup vs baseline: 1.0634x; 1.0634x over previous
#include <cuda_runtime.h>
#include <cuda_fp16.h>
#include <cstdint>
#include <math.h>

#define NB 32768      // tokens
#define ND 768        // model dim
#define NH 3072       // hidden dim
#define NE 8          // experts
#define BM 128
#define BN 128
#define BK 32
#define MAX_TILES ((NB * 2) / BM + NE)   // 520
#define PAD_ROWS (MAX_TILES * BM)        // 66560
#define NCTA 296                          // 2 CTAs/SM x 148 SMs (persistent)

#define OP_LD 40      // smem row stride (elements): 32 data + 8 pad = 80B

// ---------------- scratch (device globals; referenced ONLY by name in device
// code — never passed as kernel arguments from host) --------------------------
__device__ __half g_a16[(size_t)PAD_ROWS * ND];    // fp16(x) gathered pair rows
__device__ __half g_h16[(size_t)PAD_ROWS * NH];    // fp16(relu(h)) activations
__device__ float  g_outp[(size_t)PAD_ROWS * ND];   // per-pair expert outputs
__device__ __half g_w1t[(size_t)NE * NH * ND];     // [e][n][k] fp16
__device__ __half g_w2t[(size_t)NE * ND * NH];     // [e][n][k] fp16
__device__ int   g_pair_token[PAD_ROWS];
__device__ int   g_pairpos[NB * 2];
__device__ float g_wts[NB * 2];
__device__ int   g_eidx[NB * 2];
__device__ int   g_counts[NE];
__device__ int   g_cursor[NE];
__device__ int   g_offsets[NE];
__device__ int   g_tile_expert[MAX_TILES];
__device__ int   g_tile_segend[MAX_TILES];
__device__ int   g_work[2];                        // persistent work counters

// ---------------- PTX helpers ------------------------------------------------
__device__ __forceinline__ uint32_t smem_to_u32(const void* p) {
    uint32_t a;
    asm("{ .reg .u64 t; cvta.to.shared.u64 t, %1; cvt.u32.u64 %0, t; }"
        : "=r"(a) : "l"(p));
    return a;
}
__device__ __forceinline__ void cp_async16(uint32_t smem, const void* g) {
    asm volatile("cp.async.cg.shared.global [%0], [%1], 16;" :: "r"(smem), "l"(g));
}
#define CP_COMMIT() asm volatile("cp.async.commit_group;" ::: "memory")
#define CP_WAIT(n)  asm volatile("cp.async.wait_group %0;" :: "n"(n) : "memory")

#define MMA_F16(d, a, b) \
    asm volatile("mma.sync.aligned.m16n8k16.row.col.f32.f16.f16.f32 " \
        "{%0,%1,%2,%3}, {%4,%5,%6,%7}, {%8,%9}, {%0,%1,%2,%3};" \
        : "+f"((d)[0]), "+f"((d)[1]), "+f"((d)[2]), "+f"((d)[3]) \
        : "r"((a)[0]), "r"((a)[1]), "r"((a)[2]), "r"((a)[3]), \
          "r"((b)[0]), "r"((b)[1]))

// ---------------- init / gating / routing (proven) ---------------------------
__global__ void init_kernel() {
    if (threadIdx.x < NE) g_counts[threadIdx.x] = 0;
    if (threadIdx.x < 2)  g_work[threadIdx.x] = 0;
}

__global__ void gating_kernel(const float* __restrict__ x,
                              const float* __restrict__ Wg,
                              const float* __restrict__ bg) {
    int warp = (blockIdx.x * blockDim.x + threadIdx.x) >> 5;
    int lane = threadIdx.x & 31;
    if (warp >= NB) return;
    const float* xr = x + (size_t)warp * ND;
    float acc[8];
#pragma unroll
    for (int i = 0; i < 8; ++i) acc[i] = 0.f;
#pragma unroll 4
    for (int j = 0; j < ND / 32; ++j) {
        int d = j * 32 + lane;
        float xv = xr[d];
        const float* wr = Wg + (size_t)d * NE;
        float4 w0 = *(const float4*)(wr);
        float4 w1 = *(const float4*)(wr + 4);
        acc[0] += xv * w0.x; acc[1] += xv * w0.y;
        acc[2] += xv * w0.z; acc[3] += xv * w0.w;
        acc[4] += xv * w1.x; acc[5] += xv * w1.y;
        acc[6] += xv * w1.z; acc[7] += xv * w1.w;
    }
#pragma unroll
    for (int i = 0; i < 8; ++i)
#pragma unroll
        for (int off = 16; off > 0; off >>= 1)
            acc[i] += __shfl_xor_sync(0xFFFFFFFFu, acc[i], off);
    if (lane == 0) {
        float l[8];
#pragma unroll
        for (int i = 0; i < 8; ++i) l[i] = acc[i] + bg[i];
        int e0 = 0; float v0 = l[0];
#pragma unroll
        for (int i = 1; i < 8; ++i)
            if (l[i] > v0) { v0 = l[i]; e0 = i; }
        int e1 = -1; float v1 = -1e30f;
#pragma unroll
        for (int i = 0; i < 8; ++i)
            if (i != e0 && l[i] > v1) { v1 = l[i]; e1 = i; }
        float t  = expf(v1 - v0);
        float w0 = 1.f / (1.f + t);
        float w1 = t / (1.f + t);
        g_eidx[warp * 2 + 0] = e0;
        g_eidx[warp * 2 + 1] = e1;
        g_wts[warp * 2 + 0]  = w0;
        g_wts[warp * 2 + 1]  = w1;
        atomicAdd(&g_counts[e0], 1);
        atomicAdd(&g_counts[e1], 1);
    }
}

__global__ void route_build_kernel() {
    if (threadIdx.x == 0 && blockIdx.x == 0) {
        int off = 0, tile = 0;
        for (int e = 0; e < NE; ++e) {
            g_offsets[e] = off;
            g_cursor[e]  = 0;
            int c  = g_counts[e];
            int nt = (c + BM - 1) / BM;
            for (int i = 0; i < nt; ++i) {
                g_tile_expert[tile] = e;
                g_tile_segend[tile] = off + c;
                ++tile;
            }
            off += nt * BM;
        }
        for (; tile < MAX_TILES; ++tile) { g_tile_expert[tile] = -1; g_tile_segend[tile] = 0; }
    }
}

__global__ void assign_kernel() {
    int tid = blockIdx.x * blockDim.x + threadIdx.x;
    if (tid >= NB * 2) return;
    int b = tid >> 1;
    int e = g_eidx[tid];
    int pos = g_offsets[e] + atomicAdd(&g_cursor[e], 1);
    g_pair_token[pos] = b;
    g_pairpos[tid]    = pos;
}

// ---------------- gather x -> fp16 pair rows ---------------------------------
__global__ void gather_kernel(const float* __restrict__ x) {
    const int PER_ROW = ND / 8;
    int idx = blockIdx.x * blockDim.x + threadIdx.x;
    if (idx >= PAD_ROWS * PER_ROW) return;
    int r = idx / PER_ROW;
    int j = idx - r * PER_ROW;
    int rt = r >> 7;
    int tokv = -1;
    if (g_tile_expert[rt] >= 0 && r < g_tile_segend[rt]) tokv = g_pair_token[r];

    ushort h16[8];
    if (tokv >= 0) {
        const float* xp = x + (size_t)tokv * ND + j * 8;
        float4 a = *(const float4*)xp;
        float4 b = *(const float4*)(xp + 4);
        float v[8] = {a.x, a.y, a.z, a.w, b.x, b.y, b.z, b.w};
#pragma unroll
        for (int i = 0; i < 8; ++i)
            h16[i] = __half_as_ushort(__float2half_rn(v[i]));
    } else {
#pragma unroll
        for (int i = 0; i < 8; ++i) h16[i] = 0;
    }
    *(uint4*)(g_a16 + (size_t)r * ND + j * 8) = *(uint4*)h16;
}

// ---------------- weight transpose+convert: W[e][K][N] -> [e][N][K] fp16 -----
template<bool IS_W1>
__global__ void wconv_kernel(const float* __restrict__ W, int K, int N) {
    __shared__ float tile[32][33];
    __half* o = IS_W1 ? g_w1t : g_w2t;
    int e = blockIdx.z;
    const float* Win = W + (size_t)e * K * N;
    __half* oe = o + (size_t)e * K * N;
    int n0 = blockIdx.x * 32, k0 = blockIdx.y * 32;
    int tx = threadIdx.x, ty = threadIdx.y;
#pragma unroll
    for (int j = 0; j < 4; ++j)
        tile[ty + j * 8][tx] = Win[(size_t)(k0 + ty + j * 8) * N + n0 + tx];
    __syncthreads();
#pragma unroll
    for (int j = 0; j < 4; ++j) {
        float v = tile[tx][ty + j * 8];
        oe[(size_t)(n0 + ty + j * 8) * K + k0 + tx] = __float2half_rn(v);
    }
}

// ---------------- persistent single-product fp16 HMMA GEMM -------------------
// 296 persistent CTAs; tiles fetched via atomic counter (rt-major order keeps
// the A-row/L2 reuse of the old grid). Inner tile math identical to R14:
// 256 thr = 8 warps 2(m) x 4(n), warp tile 64x32, BK=32, fp32-acc HMMA.
template<int KTOT, bool IS_GEMM1>
__global__ __launch_bounds__(256, 2) void gemm_mma_kernel(
    const float* __restrict__ bias_all,  // b1 or b2 (harness pointer)
    int NTOT) {

    __shared__ __half sA[2][BM * OP_LD];
    __shared__ __half sB[2][BN * OP_LD];
    __shared__ int s_idx;

    const __half* Ain = IS_GEMM1 ? g_a16 : g_h16;
    const __half* Bin = IS_GEMM1 ? g_w1t : g_w2t;

    const int NXT   = NTOT / BN;
    const int TOTAL = NXT * MAX_TILES;

    int t = threadIdx.x;
    int lane = t & 31;
    int warp = t >> 5;
    int m_base = (warp & 1) * 64;
    int n_base = (warp >> 1) * 32;
    int g4   = lane >> 2;   // 0..7
    int tid4 = lane & 3;    // 0..3

    uint32_t uA = smem_to_u32(sA);
    uint32_t uB = smem_to_u32(sB);
    const uint32_t stage_b = BM * OP_LD * 2;   // bytes per stage

    for (;;) {
        if (t == 0) s_idx = atomicAdd(&g_work[IS_GEMM1 ? 0 : 1], 1);
        __syncthreads();
        int idx = s_idx;
        __syncthreads();
        if (idx >= TOTAL) return;

        int rt = idx / NXT;                 // rt-major: consecutive idx share A
        int n0 = (idx - rt * NXT) * BN;
        int e  = g_tile_expert[rt];
        if (e < 0) continue;
        int seg_end = g_tile_segend[rt];
        int r0 = rt * BM;

        const float* bias_e = bias_all + (size_t)e * NTOT + n0;

        auto issue = [&](int c, int s) {
            uint32_t off = (uint32_t)s * stage_b;
            int koff = c * BK;
#pragma unroll
            for (int r = 0; r < 2; ++r) {
                int id2 = t + r * 256;
                int row = id2 >> 2;
                int ch  = id2 & 3;
                uint32_t so = (uint32_t)(row * (OP_LD * 2) + ch * 16);
                cp_async16(uA + off + so,
                           Ain + (size_t)(r0 + row) * KTOT + koff + ch * 8);
                cp_async16(uB + off + so,
                           Bin + ((size_t)e * NTOT + n0 + row) * KTOT + koff + ch * 8);
            }
        };

        float acc[4][4][4];
#pragma unroll
        for (int i = 0; i < 4; ++i)
#pragma unroll
            for (int j = 0; j < 4; ++j)
#pragma unroll
                for (int q = 0; q < 4; ++q) acc[i][j][q] = 0.f;

        const int NC = KTOT / BK;

        issue(0, 0); CP_COMMIT();

        for (int c = 0; c < NC; ++c) {
            int s = c & 1;
            if (c + 1 < NC) {
                issue(c + 1, s ^ 1); CP_COMMIT();
                CP_WAIT(1);
            } else {
                CP_WAIT(0);
            }
            __syncthreads();

            const __half* pA = sA[s];
            const __half* pB = sB[s];

#pragma unroll
            for (int ks = 0; ks < 2; ++ks) {
                int kadd = ks * 16;
                uint32_t fb[4][2];
#pragma unroll
                for (int j = 0; j < 4; ++j) {
                    int nrow = (n_base + j * 8 + g4) * OP_LD + kadd + tid4 * 2;
                    fb[j][0] = *(const uint32_t*)&pB[nrow];
                    fb[j][1] = *(const uint32_t*)&pB[nrow + 8];
                }
#pragma unroll
                for (int i = 0; i < 4; ++i) {
                    uint32_t fa[4];
                    int rlo = (m_base + i * 16 + g4) * OP_LD + kadd + tid4 * 2;
                    int rhi = rlo + 8 * OP_LD;
                    fa[0] = *(const uint32_t*)&pA[rlo];
                    fa[1] = *(const uint32_t*)&pA[rhi];
                    fa[2] = *(const uint32_t*)&pA[rlo + 8];
                    fa[3] = *(const uint32_t*)&pA[rhi + 8];
#pragma unroll
                    for (int j = 0; j < 4; ++j) MMA_F16(acc[i][j], fa, fb[j]);
                }
            }
            __syncthreads();
        }

        // ---- epilogue: direct from accumulator regs (no smem) ---------------
#pragma unroll
        for (int j = 0; j < 4; ++j) {
            int coll = n_base + j * 8 + tid4 * 2;
            float b0 = bias_e[coll];
            float b1 = bias_e[coll + 1];
            int gcol = n0 + coll;
#pragma unroll
            for (int i = 0; i < 4; ++i) {
                int row0 = r0 + m_base + i * 16 + g4;
                int row1 = row0 + 8;
                float v0 = acc[i][j][0] + b0;
                float v1 = acc[i][j][1] + b1;
                float v2 = acc[i][j][2] + b0;
                float v3 = acc[i][j][3] + b1;
                if (IS_GEMM1) {
                    v0 = fmaxf(v0, 0.f); v1 = fmaxf(v1, 0.f);
                    v2 = fmaxf(v2, 0.f); v3 = fmaxf(v3, 0.f);
                    if (row0 < seg_end) {
                        uint32_t p = (uint32_t)__half_as_ushort(__float2half_rn(v0)) |
                                     ((uint32_t)__half_as_ushort(__float2half_rn(v1)) << 16);
                        *(uint32_t*)(g_h16 + (size_t)row0 * NH + gcol) = p;
                    }
                    if (row1 < seg_end) {
                        uint32_t p = (uint32_t)__half_as_ushort(__float2half_rn(v2)) |
                                     ((uint32_t)__half_as_ushort(__float2half_rn(v3)) << 16);
                        *(uint32_t*)(g_h16 + (size_t)row1 * NH + gcol) = p;
                    }
                } else {
                    if (row0 < seg_end) {
                        float2 p; p.x = v0; p.y = v1;
                        *(float2*)(g_outp + (size_t)row0 * ND + gcol) = p;
                    }
                    if (row1 < seg_end) {
                        float2 p; p.x = v2; p.y = v3;
                        *(float2*)(g_outp + (size_t)row1 * ND + gcol) = p;
                    }
                }
            }
        }
        __syncthreads();   // protect s_idx / smem before next tile fetch
    }
}

// ---------------- combine ----------------------------------------------------
__global__ void combine_kernel(float* __restrict__ y) {
    const int QD = ND / 4;
    int tid = blockIdx.x * blockDim.x + threadIdx.x;
    if (tid >= NB * QD) return;
    int b = tid / QD;
    int q = tid - b * QD;
    int p0 = g_pairpos[b * 2 + 0];
    int p1 = g_pairpos[b * 2 + 1];
    float w0 = g_wts[b * 2 + 0];
    float w1 = g_wts[b * 2 + 1];
    float4 o0 = ((const float4*)(g_outp + (size_t)p0 * ND))[q];
    float4 o1 = ((const float4*)(g_outp + (size_t)p1 * ND))[q];
    float4 r;
    r.x = w0 * o0.x + w1 * o1.x;
    r.y = w0 * o0.y + w1 * o1.y;
    r.z = w0 * o0.z + w1 * o1.z;
    r.w = w0 * o0.w + w1 * o1.w;
    ((float4*)y)[tid] = r;
}

// ---------------- launch ------------------------------------------------------
extern "C" void kernel_launch(void* const* d_in, const int* in_sizes, int n_in,
                              void* d_out, int out_size) {
    const float* x  = (const float*)d_in[0];
    const float* Wg = (const float*)d_in[1];
    const float* bg = (const float*)d_in[2];
    const float* W1 = (const float*)d_in[3];
    const float* b1 = (const float*)d_in[4];
    const float* W2 = (const float*)d_in[5];
    const float* b2 = (const float*)d_in[6];
    float* y = (float*)d_out;

    init_kernel<<<1, 32>>>();
    gating_kernel<<<(NB * 32) / 256, 256>>>(x, Wg, bg);
    route_build_kernel<<<1, 1>>>();
    assign_kernel<<<(NB * 2) / 256, 256>>>();

    // one-time conversions
    {
        dim3 g(NH / 32, ND / 32, NE);
        wconv_kernel<true><<<g, dim3(32, 8)>>>(W1, ND, NH);
    }
    {
        dim3 g(ND / 32, NH / 32, NE);
        wconv_kernel<false><<<g, dim3(32, 8)>>>(W2, NH, ND);
    }
    {
        int total = PAD_ROWS * (ND / 8);
        gather_kernel<<<(total + 255) / 256, 256>>>(x);
    }

    // GEMM1 (persistent): relu(fp16(x) @ fp16(W1) + b1) -> g_h16
    gemm_mma_kernel<ND, true><<<NCTA, 256>>>(b1, NH);
    // GEMM2 (persistent): g_h16 @ fp16(W2) + b2 -> g_outp
    gemm_mma_kernel<NH, false><<<NCTA, 256>>>(b2, ND);

    combine_kernel<<<(NB * (ND / 4) + 255) / 256, 256>>>(y);
}

// round 17
// speedup vs baseline: 1.1488x; 1.0802x over previous
#include <cuda_runtime.h>
#include <cuda_fp16.h>
#include <cstdint>
#include <math.h>

#define NB 32768      // tokens
#define ND 768        // model dim
#define NH 3072       // hidden dim
#define NE 8          // experts
#define BM 128
#define BN 128
#define BK 32
#define MAX_TILES ((NB * 2) / BM + NE)   // 520
#define PAD_ROWS (MAX_TILES * BM)        // 66560
#define NCTA 296                          // 2 CTAs/SM x 148 SMs (persistent)

#define OP_LD 40      // smem row stride (elements): 32 data + 8 pad = 80B

// ---------------- scratch (device globals; referenced ONLY by name in device
// code — never passed as kernel arguments from host) --------------------------
__device__ __half g_a16[(size_t)PAD_ROWS * ND];    // fp16(x) gathered pair rows
__device__ __half g_h16[(size_t)PAD_ROWS * NH];    // fp16(relu(h)) activations
__device__ float  g_outp[(size_t)PAD_ROWS * ND];   // per-pair expert outputs
__device__ __half g_w1t[(size_t)NE * NH * ND];     // [e][n][k] fp16
__device__ __half g_w2t[(size_t)NE * ND * NH];     // [e][n][k] fp16
__device__ int   g_pair_token[PAD_ROWS];
__device__ int   g_pairpos[NB * 2];
__device__ float g_wts[NB * 2];
__device__ int   g_eidx[NB * 2];
__device__ int   g_counts[NE];
__device__ int   g_cursor[NE];
__device__ int   g_offsets[NE];
__device__ int   g_tile_expert[MAX_TILES];
__device__ int   g_tile_segend[MAX_TILES];
__device__ int   g_work[2];                        // persistent work counters

// ---------------- PTX helpers ------------------------------------------------
__device__ __forceinline__ uint32_t smem_to_u32(const void* p) {
    uint32_t a;
    asm("{ .reg .u64 t; cvta.to.shared.u64 t, %1; cvt.u32.u64 %0, t; }"
        : "=r"(a) : "l"(p));
    return a;
}
__device__ __forceinline__ void cp_async16(uint32_t smem, const void* g) {
    asm volatile("cp.async.cg.shared.global [%0], [%1], 16;" :: "r"(smem), "l"(g));
}
#define CP_COMMIT() asm volatile("cp.async.commit_group;" ::: "memory")
#define CP_WAIT(n)  asm volatile("cp.async.wait_group %0;" :: "n"(n) : "memory")

#define MMA_F16(d, a, b) \
    asm volatile("mma.sync.aligned.m16n8k16.row.col.f32.f16.f16.f32 " \
        "{%0,%1,%2,%3}, {%4,%5,%6,%7}, {%8,%9}, {%0,%1,%2,%3};" \
        : "+f"((d)[0]), "+f"((d)[1]), "+f"((d)[2]), "+f"((d)[3]) \
        : "r"((a)[0]), "r"((a)[1]), "r"((a)[2]), "r"((a)[3]), \
          "r"((b)[0]), "r"((b)[1]))

#define LDMX4(r, addr) \
    asm volatile("ldmatrix.sync.aligned.m8n8.x4.shared.b16 {%0,%1,%2,%3}, [%4];" \
        : "=r"((r)[0]), "=r"((r)[1]), "=r"((r)[2]), "=r"((r)[3]) : "r"(addr))

// ---------------- init / gating / routing (proven) ---------------------------
__global__ void init_kernel() {
    if (threadIdx.x < NE) g_counts[threadIdx.x] = 0;
    if (threadIdx.x < 2)  g_work[threadIdx.x] = 0;
}

__global__ void gating_kernel(const float* __restrict__ x,
                              const float* __restrict__ Wg,
                              const float* __restrict__ bg) {
    int warp = (blockIdx.x * blockDim.x + threadIdx.x) >> 5;
    int lane = threadIdx.x & 31;
    if (warp >= NB) return;
    const float* xr = x + (size_t)warp * ND;
    float acc[8];
#pragma unroll
    for (int i = 0; i < 8; ++i) acc[i] = 0.f;
#pragma unroll 4
    for (int j = 0; j < ND / 32; ++j) {
        int d = j * 32 + lane;
        float xv = xr[d];
        const float* wr = Wg + (size_t)d * NE;
        float4 w0 = *(const float4*)(wr);
        float4 w1 = *(const float4*)(wr + 4);
        acc[0] += xv * w0.x; acc[1] += xv * w0.y;
        acc[2] += xv * w0.z; acc[3] += xv * w0.w;
        acc[4] += xv * w1.x; acc[5] += xv * w1.y;
        acc[6] += xv * w1.z; acc[7] += xv * w1.w;
    }
#pragma unroll
    for (int i = 0; i < 8; ++i)
#pragma unroll
        for (int off = 16; off > 0; off >>= 1)
            acc[i] += __shfl_xor_sync(0xFFFFFFFFu, acc[i], off);
    if (lane == 0) {
        float l[8];
#pragma unroll
        for (int i = 0; i < 8; ++i) l[i] = acc[i] + bg[i];
        int e0 = 0; float v0 = l[0];
#pragma unroll
        for (int i = 1; i < 8; ++i)
            if (l[i] > v0) { v0 = l[i]; e0 = i; }
        int e1 = -1; float v1 = -1e30f;
#pragma unroll
        for (int i = 0; i < 8; ++i)
            if (i != e0 && l[i] > v1) { v1 = l[i]; e1 = i; }
        float t  = expf(v1 - v0);
        float w0 = 1.f / (1.f + t);
        float w1 = t / (1.f + t);
        g_eidx[warp * 2 + 0] = e0;
        g_eidx[warp * 2 + 1] = e1;
        g_wts[warp * 2 + 0]  = w0;
        g_wts[warp * 2 + 1]  = w1;
        atomicAdd(&g_counts[e0], 1);
        atomicAdd(&g_counts[e1], 1);
    }
}

__global__ void route_build_kernel() {
    if (threadIdx.x == 0 && blockIdx.x == 0) {
        int off = 0, tile = 0;
        for (int e = 0; e < NE; ++e) {
            g_offsets[e] = off;
            g_cursor[e]  = 0;
            int c  = g_counts[e];
            int nt = (c + BM - 1) / BM;
            for (int i = 0; i < nt; ++i) {
                g_tile_expert[tile] = e;
                g_tile_segend[tile] = off + c;
                ++tile;
            }
            off += nt * BM;
        }
        for (; tile < MAX_TILES; ++tile) { g_tile_expert[tile] = -1; g_tile_segend[tile] = 0; }
    }
}

__global__ void assign_kernel() {
    int tid = blockIdx.x * blockDim.x + threadIdx.x;
    if (tid >= NB * 2) return;
    int b = tid >> 1;
    int e = g_eidx[tid];
    int pos = g_offsets[e] + atomicAdd(&g_cursor[e], 1);
    g_pair_token[pos] = b;
    g_pairpos[tid]    = pos;
}

// ---------------- gather x -> fp16 pair rows ---------------------------------
__global__ void gather_kernel(const float* __restrict__ x) {
    const int PER_ROW = ND / 8;
    int idx = blockIdx.x * blockDim.x + threadIdx.x;
    if (idx >= PAD_ROWS * PER_ROW) return;
    int r = idx / PER_ROW;
    int j = idx - r * PER_ROW;
    int rt = r >> 7;
    int tokv = -1;
    if (g_tile_expert[rt] >= 0 && r < g_tile_segend[rt]) tokv = g_pair_token[r];

    ushort h16[8];
    if (tokv >= 0) {
        const float* xp = x + (size_t)tokv * ND + j * 8;
        float4 a = *(const float4*)xp;
        float4 b = *(const float4*)(xp + 4);
        float v[8] = {a.x, a.y, a.z, a.w, b.x, b.y, b.z, b.w};
#pragma unroll
        for (int i = 0; i < 8; ++i)
            h16[i] = __half_as_ushort(__float2half_rn(v[i]));
    } else {
#pragma unroll
        for (int i = 0; i < 8; ++i) h16[i] = 0;
    }
    *(uint4*)(g_a16 + (size_t)r * ND + j * 8) = *(uint4*)h16;
}

// ---------------- weight transpose+convert: W[e][K][N] -> [e][N][K] fp16 -----
template<bool IS_W1>
__global__ void wconv_kernel(const float* __restrict__ W, int K, int N) {
    __shared__ float tile[32][33];
    __half* o = IS_W1 ? g_w1t : g_w2t;
    int e = blockIdx.z;
    const float* Win = W + (size_t)e * K * N;
    __half* oe = o + (size_t)e * K * N;
    int n0 = blockIdx.x * 32, k0 = blockIdx.y * 32;
    int tx = threadIdx.x, ty = threadIdx.y;
#pragma unroll
    for (int j = 0; j < 4; ++j)
        tile[ty + j * 8][tx] = Win[(size_t)(k0 + ty + j * 8) * N + n0 + tx];
    __syncthreads();
#pragma unroll
    for (int j = 0; j < 4; ++j) {
        float v = tile[tx][ty + j * 8];
        oe[(size_t)(n0 + ty + j * 8) * K + k0 + tx] = __float2half_rn(v);
    }
}

// ---------------- persistent fp16 HMMA GEMM, ldmatrix fragments --------------
// 296 persistent CTAs; tiles via atomic counter (rt-major keeps A/L2 reuse).
// 256 thr = 8 warps 2(m) x 4(n), warp tile 64x32, BK=32, fp32-acc HMMA.
// Fragments via ldmatrix.x4: A (i,ks) in 1 instr; B j-pair (jp,ks) in 1 instr.
// Byte-identical fragment values vs the R16 scalar-LDS loads.
template<int KTOT, bool IS_GEMM1>
__global__ __launch_bounds__(256, 2) void gemm_mma_kernel(
    const float* __restrict__ bias_all,  // b1 or b2 (harness pointer)
    int NTOT) {

    __shared__ __half sA[2][BM * OP_LD];
    __shared__ __half sB[2][BN * OP_LD];
    __shared__ int s_idx;

    const __half* Ain = IS_GEMM1 ? g_a16 : g_h16;
    const __half* Bin = IS_GEMM1 ? g_w1t : g_w2t;

    const int NXT   = NTOT / BN;
    const int TOTAL = NXT * MAX_TILES;

    int t = threadIdx.x;
    int lane = t & 31;
    int warp = t >> 5;
    int m_base = (warp & 1) * 64;
    int n_base = (warp >> 1) * 32;
    int g4   = lane >> 2;   // 0..7
    int tid4 = lane & 3;    // 0..3

    uint32_t uA = smem_to_u32(sA);
    uint32_t uB = smem_to_u32(sB);
    const uint32_t stage_b = BM * OP_LD * 2;   // bytes per stage

    // ldmatrix per-lane base offsets (bytes within a stage), PTX x4 order:
    // A (i,ks): m0/m1 = k-chunk0 rows 0-7/8-15, m2/m3 = k-chunk1.
    int r8 = lane & 7;
    uint32_t aoff = (uint32_t)(((m_base + ((lane >> 3) & 1) * 8 + r8) * OP_LD +
                                (lane >> 4) * 8) * 2);
    // B (jp,ks): m0/m1 = row-block jp*16+0..7 kc0/kc1, m2/m3 = +8 rows kc0/kc1.
    uint32_t boff = (uint32_t)(((n_base + (lane >> 4) * 8 + r8) * OP_LD +
                                ((lane >> 3) & 1) * 8) * 2);

    for (;;) {
        if (t == 0) s_idx = atomicAdd(&g_work[IS_GEMM1 ? 0 : 1], 1);
        __syncthreads();
        int idx = s_idx;
        __syncthreads();
        if (idx >= TOTAL) return;

        int rt = idx / NXT;                 // rt-major: consecutive idx share A
        int n0 = (idx - rt * NXT) * BN;
        int e  = g_tile_expert[rt];
        if (e < 0) continue;
        int seg_end = g_tile_segend[rt];
        int r0 = rt * BM;

        const float* bias_e = bias_all + (size_t)e * NTOT + n0;

        auto issue = [&](int c, int s) {
            uint32_t off = (uint32_t)s * stage_b;
            int koff = c * BK;
#pragma unroll
            for (int r = 0; r < 2; ++r) {
                int id2 = t + r * 256;
                int row = id2 >> 2;
                int ch  = id2 & 3;
                uint32_t so = (uint32_t)(row * (OP_LD * 2) + ch * 16);
                cp_async16(uA + off + so,
                           Ain + (size_t)(r0 + row) * KTOT + koff + ch * 8);
                cp_async16(uB + off + so,
                           Bin + ((size_t)e * NTOT + n0 + row) * KTOT + koff + ch * 8);
            }
        };

        float acc[4][4][4];
#pragma unroll
        for (int i = 0; i < 4; ++i)
#pragma unroll
            for (int j = 0; j < 4; ++j)
#pragma unroll
                for (int q = 0; q < 4; ++q) acc[i][j][q] = 0.f;

        const int NC = KTOT / BK;

        issue(0, 0); CP_COMMIT();

        for (int c = 0; c < NC; ++c) {
            int s = c & 1;
            if (c + 1 < NC) {
                issue(c + 1, s ^ 1); CP_COMMIT();
                CP_WAIT(1);
            } else {
                CP_WAIT(0);
            }
            __syncthreads();

            uint32_t stA = uA + (uint32_t)s * stage_b;
            uint32_t stB = uB + (uint32_t)s * stage_b;

#pragma unroll
            for (int ks = 0; ks < 2; ++ks) {
                uint32_t kadd = ks * 32;          // 16 elements = 32 bytes
                // B fragments: 2 ldmatrix.x4, each yields fb for a j-pair
                uint32_t fb[4][2];
#pragma unroll
                for (int jp = 0; jp < 2; ++jp) {
                    uint32_t r4[4];
                    LDMX4(r4, stB + boff + kadd + (uint32_t)(jp * 16 * OP_LD * 2));
                    fb[2 * jp + 0][0] = r4[0];
                    fb[2 * jp + 0][1] = r4[1];
                    fb[2 * jp + 1][0] = r4[2];
                    fb[2 * jp + 1][1] = r4[3];
                }
#pragma unroll
                for (int i = 0; i < 4; ++i) {
                    uint32_t fa[4];
                    LDMX4(fa, stA + aoff + kadd + (uint32_t)(i * 16 * OP_LD * 2));
#pragma unroll
                    for (int j = 0; j < 4; ++j) MMA_F16(acc[i][j], fa, fb[j]);
                }
            }
            __syncthreads();
        }

        // ---- epilogue: direct from accumulator regs -------------------------
#pragma unroll
        for (int j = 0; j < 4; ++j) {
            int coll = n_base + j * 8 + tid4 * 2;
            float b0 = bias_e[coll];
            float b1 = bias_e[coll + 1];
            int gcol = n0 + coll;
#pragma unroll
            for (int i = 0; i < 4; ++i) {
                int row0 = r0 + m_base + i * 16 + g4;
                int row1 = row0 + 8;
                float v0 = acc[i][j][0] + b0;
                float v1 = acc[i][j][1] + b1;
                float v2 = acc[i][j][2] + b0;
                float v3 = acc[i][j][3] + b1;
                if (IS_GEMM1) {
                    v0 = fmaxf(v0, 0.f); v1 = fmaxf(v1, 0.f);
                    v2 = fmaxf(v2, 0.f); v3 = fmaxf(v3, 0.f);
                    if (row0 < seg_end) {
                        uint32_t p = (uint32_t)__half_as_ushort(__float2half_rn(v0)) |
                                     ((uint32_t)__half_as_ushort(__float2half_rn(v1)) << 16);
                        *(uint32_t*)(g_h16 + (size_t)row0 * NH + gcol) = p;
                    }
                    if (row1 < seg_end) {
                        uint32_t p = (uint32_t)__half_as_ushort(__float2half_rn(v2)) |
                                     ((uint32_t)__half_as_ushort(__float2half_rn(v3)) << 16);
                        *(uint32_t*)(g_h16 + (size_t)row1 * NH + gcol) = p;
                    }
                } else {
                    if (row0 < seg_end) {
                        float2 p; p.x = v0; p.y = v1;
                        *(float2*)(g_outp + (size_t)row0 * ND + gcol) = p;
                    }
                    if (row1 < seg_end) {
                        float2 p; p.x = v2; p.y = v3;
                        *(float2*)(g_outp + (size_t)row1 * ND + gcol) = p;
                    }
                }
            }
        }
        __syncthreads();   // protect s_idx / smem before next tile fetch
    }
}

// ---------------- combine ----------------------------------------------------
__global__ void combine_kernel(float* __restrict__ y) {
    const int QD = ND / 4;
    int tid = blockIdx.x * blockDim.x + threadIdx.x;
    if (tid >= NB * QD) return;
    int b = tid / QD;
    int q = tid - b * QD;
    int p0 = g_pairpos[b * 2 + 0];
    int p1 = g_pairpos[b * 2 + 1];
    float w0 = g_wts[b * 2 + 0];
    float w1 = g_wts[b * 2 + 1];
    float4 o0 = ((const float4*)(g_outp + (size_t)p0 * ND))[q];
    float4 o1 = ((const float4*)(g_outp + (size_t)p1 * ND))[q];
    float4 r;
    r.x = w0 * o0.x + w1 * o1.x;
    r.y = w0 * o0.y + w1 * o1.y;
    r.z = w0 * o0.z + w1 * o1.z;
    r.w = w0 * o0.w + w1 * o1.w;
    ((float4*)y)[tid] = r;
}

// ---------------- launch ------------------------------------------------------
extern "C" void kernel_launch(void* const* d_in, const int* in_sizes, int n_in,
                              void* d_out, int out_size) {
    const float* x  = (const float*)d_in[0];
    const float* Wg = (const float*)d_in[1];
    const float* bg = (const float*)d_in[2];
    const float* W1 = (const float*)d_in[3];
    const float* b1 = (const float*)d_in[4];
    const float* W2 = (const float*)d_in[5];
    const float* b2 = (const float*)d_in[6];
    float* y = (float*)d_out;

    init_kernel<<<1, 32>>>();
    gating_kernel<<<(NB * 32) / 256, 256>>>(x, Wg, bg);
    route_build_kernel<<<1, 1>>>();
    assign_kernel<<<(NB * 2) / 256, 256>>>();

    // one-time conversions
    {
        dim3 g(NH / 32, ND / 32, NE);
        wconv_kernel<true><<<g, dim3(32, 8)>>>(W1, ND, NH);
    }
    {
        dim3 g(ND / 32, NH / 32, NE);
        wconv_kernel<false><<<g, dim3(32, 8)>>>(W2, NH, ND);
    }
    {
        int total = PAD_ROWS * (ND / 8);
        gather_kernel<<<(total + 255) / 256, 256>>>(x);
    }

    // GEMM1 (persistent): relu(fp16(x) @ fp16(W1) + b1) -> g_h16
    gemm_mma_kernel<ND, true><<<NCTA, 256>>>(b1, NH);
    // GEMM2 (persistent): g_h16 @ fp16(W2) + b2 -> g_outp
    gemm_mma_kernel<NH, false><<<NCTA, 256>>>(b2, ND);

    combine_kernel<<<(NB * (ND / 4) + 255) / 256, 256>>>(y);
}